// round 2
// baseline (speedup 1.0000x reference)
#include <cuda_runtime.h>
#include <math.h>

// Problem constants
#define BB 8
#define LL 2048
#define DD 1024
#define FF 4096
#define MM (BB*LL)        // 16384 rows
#define TOPK 7
#define LMASK (LL-1)

// ---------------- scratch (device globals; no allocation) ----------------
__device__ float g_q[(size_t)MM*DD];            // q  -> later attn out
__device__ float g_k[(size_t)MM*DD];            // k  -> later x1
__device__ float g_v[(size_t)MM*DD];            // v  -> later y (c2 out)
__device__ float g_G[(size_t)BB*LL*LL];         // Gram -> later roll output (first 64MB)
__device__ float g_h[(size_t)MM*FF];            // FFN hidden
__device__ float g_part[BB*8*LL];               // lag partial sums
__device__ float g_mv[BB*LL];                   // mean_value
__device__ float g_w[BB*8];                     // softmax weights
__device__ int   g_delay[8];                    // delays (from batch 0)

// ---------------- generic fp32 SGEMM: C = A(MxK) * B + bias (+relu) ------
// TRANSB=false: B is K x N row-major.  TRANSB=true: B is N x K row-major.
template<bool TRANSB, bool RELU>
__global__ __launch_bounds__(256)
void sgemm(const float* __restrict__ A, const float* __restrict__ B,
           float* __restrict__ C, const float* __restrict__ bias,
           int M, int N, int K, size_t sA, size_t sB, size_t sC)
{
    A += (size_t)blockIdx.z * sA;
    B += (size_t)blockIdx.z * sB;
    C += (size_t)blockIdx.z * sC;

    __shared__ float As[8][128];
    __shared__ float Bs[8][128];

    const int tid = threadIdx.x;
    const int bm  = blockIdx.y * 128;
    const int bn  = blockIdx.x * 128;
    const int tx  = (tid & 15) * 8;     // 0..120
    const int ty  = (tid >> 4) * 8;     // 0..120
    const int lr  = tid >> 1;           // 0..127 (A / transB load row)
    const int lc  = (tid & 1) * 4;      // 0 or 4
    const int br  = tid >> 5;           // 0..7  (B load row, non-trans)
    const int bc  = (tid & 31) * 4;     // 0..124

    float acc[8][8];
    #pragma unroll
    for (int i = 0; i < 8; i++)
        #pragma unroll
        for (int j = 0; j < 8; j++) acc[i][j] = 0.f;

    for (int k0 = 0; k0 < K; k0 += 8) {
        float4 a4 = *(const float4*)(A + (size_t)(bm + lr) * K + k0 + lc);
        As[lc+0][lr] = a4.x; As[lc+1][lr] = a4.y;
        As[lc+2][lr] = a4.z; As[lc+3][lr] = a4.w;
        if (TRANSB) {
            float4 b4 = *(const float4*)(B + (size_t)(bn + lr) * K + k0 + lc);
            Bs[lc+0][lr] = b4.x; Bs[lc+1][lr] = b4.y;
            Bs[lc+2][lr] = b4.z; Bs[lc+3][lr] = b4.w;
        } else {
            float4 b4 = *(const float4*)(B + (size_t)(k0 + br) * N + bn + bc);
            *(float4*)&Bs[br][bc] = b4;
        }
        __syncthreads();
        #pragma unroll
        for (int kk = 0; kk < 8; kk++) {
            float4 a0 = *(const float4*)&As[kk][ty];
            float4 a1 = *(const float4*)&As[kk][ty+4];
            float4 b0 = *(const float4*)&Bs[kk][tx];
            float4 b1 = *(const float4*)&Bs[kk][tx+4];
            float af[8] = {a0.x,a0.y,a0.z,a0.w,a1.x,a1.y,a1.z,a1.w};
            float bf[8] = {b0.x,b0.y,b0.z,b0.w,b1.x,b1.y,b1.z,b1.w};
            #pragma unroll
            for (int i = 0; i < 8; i++)
                #pragma unroll
                for (int j = 0; j < 8; j++)
                    acc[i][j] = fmaf(af[i], bf[j], acc[i][j]);
        }
        __syncthreads();
    }

    #pragma unroll
    for (int i = 0; i < 8; i++) {
        size_t row = (size_t)(bm + ty + i);
        #pragma unroll
        for (int j = 0; j < 8; j += 4) {
            float4 o;
            o.x = acc[i][j+0]; o.y = acc[i][j+1];
            o.z = acc[i][j+2]; o.w = acc[i][j+3];
            if (bias) {
                o.x += bias[bn+tx+j+0]; o.y += bias[bn+tx+j+1];
                o.z += bias[bn+tx+j+2]; o.w += bias[bn+tx+j+3];
            }
            if (RELU) {
                o.x = fmaxf(o.x, 0.f); o.y = fmaxf(o.y, 0.f);
                o.z = fmaxf(o.z, 0.f); o.w = fmaxf(o.w, 0.f);
            }
            *(float4*)(C + row * N + bn + tx + j) = o;
        }
    }
}

// ---- mean_value: wrapped-diagonal reduction of the Gram matrix ----------
// g_part[b][tc][l] = sum_{t in chunk tc} G[b][t][(t-l) & LMASK]
__global__ void lag_partial()
{
    int b  = blockIdx.z;
    int tc = blockIdx.y;
    int l  = blockIdx.x * 256 + threadIdx.x;
    const float* Gb = g_G + (size_t)b * LL * LL;
    int t0 = tc * 256;
    float s = 0.f;
    #pragma unroll 4
    for (int t = t0; t < t0 + 256; ++t)
        s += Gb[(size_t)t * LL + ((t - l) & LMASK)];
    g_part[(b * 8 + tc) * LL + l] = s;
}

__global__ void lag_reduce()
{
    int idx = blockIdx.x * 256 + threadIdx.x;   // b*LL + l
    int b = idx >> 11;
    int l = idx & LMASK;
    float s = 0.f;
    #pragma unroll
    for (int tc = 0; tc < 8; tc++) s += g_part[(b * 8 + tc) * LL + l];
    g_mv[idx] = s * (1.f / (float)DD);
}

// ---- top-7 + softmax (per batch); batch 0 publishes delays --------------
__global__ void topk_softmax()
{
    int b = blockIdx.x;
    int tid = threadIdx.x;
    __shared__ float vals[LL];
    __shared__ float rv[256];
    __shared__ int   ri[256];
    __shared__ float topv[TOPK];
    __shared__ int   topi[TOPK];

    for (int i = tid; i < LL; i += 256) vals[i] = g_mv[b * LL + i];
    __syncthreads();

    for (int it = 0; it < TOPK; ++it) {
        float bv = -INFINITY; int bi = 0;
        for (int i = tid; i < LL; i += 256) {
            float v = vals[i];
            if (v > bv) { bv = v; bi = i; }
        }
        rv[tid] = bv; ri[tid] = bi;
        __syncthreads();
        for (int s = 128; s > 0; s >>= 1) {
            if (tid < s) {
                if (rv[tid+s] > rv[tid] ||
                    (rv[tid+s] == rv[tid] && ri[tid+s] < ri[tid])) {
                    rv[tid] = rv[tid+s]; ri[tid] = ri[tid+s];
                }
            }
            __syncthreads();
        }
        if (tid == 0) {
            topv[it] = rv[0]; topi[it] = ri[0];
            vals[ri[0]] = -INFINITY;
        }
        __syncthreads();
    }

    if (tid == 0) {
        float mx = topv[0];
        float e[TOPK], s = 0.f;
        #pragma unroll
        for (int i = 0; i < TOPK; i++) { e[i] = expf(topv[i] - mx); s += e[i]; }
        float inv = 1.f / s;
        #pragma unroll
        for (int i = 0; i < TOPK; i++) g_w[b * 8 + i] = e[i] * inv;
        if (b == 0)
            #pragma unroll
            for (int i = 0; i < TOPK; i++) g_delay[i] = topi[i];
    }
}

// ---- delay-aggregated value: out[b,l,:] = sum_i w[b,i]*v[b,(l+d_i)%L,:] --
// output written into g_G (Gram no longer needed)
__global__ void roll_combine()
{
    int l = blockIdx.x, b = blockIdx.y;
    int tid = threadIdx.x;
    float w[TOPK]; int rows[TOPK];
    #pragma unroll
    for (int i = 0; i < TOPK; i++) {
        w[i] = g_w[b * 8 + i];
        rows[i] = (l + g_delay[i]) & LMASK;
    }
    int d = tid * 4;
    float4 acc = make_float4(0.f, 0.f, 0.f, 0.f);
    #pragma unroll
    for (int i = 0; i < TOPK; i++) {
        float4 v4 = *(const float4*)(g_v + ((size_t)(b * LL + rows[i])) * DD + d);
        acc.x = fmaf(w[i], v4.x, acc.x);
        acc.y = fmaf(w[i], v4.y, acc.y);
        acc.z = fmaf(w[i], v4.z, acc.z);
        acc.w = fmaf(w[i], v4.w, acc.w);
    }
    *(float4*)(g_G + ((size_t)(b * LL + l)) * DD + d) = acc;
}

// ---- out = LayerNorm(A + B) * gamma + beta (row = 1024) ------------------
__global__ void add_ln(const float* __restrict__ A, const float* __restrict__ Bv,
                       const float* __restrict__ gamma, const float* __restrict__ beta,
                       float* __restrict__ out)
{
    int row = blockIdx.x;
    int tid = threadIdx.x;
    const float* pa = A  + (size_t)row * DD;
    const float* pb = Bv + (size_t)row * DD;
    __shared__ float red[256];

    float v[4];
    float s = 0.f;
    #pragma unroll
    for (int j = 0; j < 4; j++) {
        int c = tid + j * 256;
        v[j] = pa[c] + pb[c];
        s += v[j];
    }
    red[tid] = s; __syncthreads();
    for (int st = 128; st > 0; st >>= 1) {
        if (tid < st) red[tid] += red[tid + st];
        __syncthreads();
    }
    float mean = red[0] * (1.f / (float)DD);
    __syncthreads();

    float vs = 0.f;
    #pragma unroll
    for (int j = 0; j < 4; j++) { float d = v[j] - mean; vs += d * d; }
    red[tid] = vs; __syncthreads();
    for (int st = 128; st > 0; st >>= 1) {
        if (tid < st) red[tid] += red[tid + st];
        __syncthreads();
    }
    float rstd = rsqrtf(red[0] * (1.f / (float)DD) + 1e-6f);

    float* po = out + (size_t)row * DD;
    #pragma unroll
    for (int j = 0; j < 4; j++) {
        int c = tid + j * 256;
        po[c] = (v[j] - mean) * rstd * gamma[c] + beta[c];
    }
}

// -------------------------------------------------------------------------
extern "C" void kernel_launch(void* const* d_in, const int* in_sizes, int n_in,
                              void* d_out, int out_size)
{
    const float* x     = (const float*)d_in[0];
    const float* Wq    = (const float*)d_in[1];
    const float* bq    = (const float*)d_in[2];
    const float* Wk    = (const float*)d_in[3];
    const float* bk    = (const float*)d_in[4];
    const float* Wv    = (const float*)d_in[5];
    const float* bv    = (const float*)d_in[6];
    const float* Wo    = (const float*)d_in[7];
    const float* bo    = (const float*)d_in[8];
    const float* ln1g  = (const float*)d_in[9];
    const float* ln1b  = (const float*)d_in[10];
    const float* c1w   = (const float*)d_in[11];
    const float* c1b   = (const float*)d_in[12];
    const float* c2w   = (const float*)d_in[13];
    const float* c2b   = (const float*)d_in[14];
    const float* ln2g  = (const float*)d_in[15];
    const float* ln2b  = (const float*)d_in[16];
    float* out = (float*)d_out;

    float *q, *k, *v, *G, *h;
    cudaGetSymbolAddress((void**)&q, g_q);
    cudaGetSymbolAddress((void**)&k, g_k);
    cudaGetSymbolAddress((void**)&v, g_v);
    cudaGetSymbolAddress((void**)&G, g_G);
    cudaGetSymbolAddress((void**)&h, g_h);

    // 1) QKV projections (fp32 GEMMs)
    sgemm<false,false><<<dim3(DD/128, MM/128, 1), 256>>>(x, Wq, q, bq, MM, DD, DD, 0, 0, 0);
    sgemm<false,false><<<dim3(DD/128, MM/128, 1), 256>>>(x, Wk, k, bk, MM, DD, DD, 0, 0, 0);
    sgemm<false,false><<<dim3(DD/128, MM/128, 1), 256>>>(x, Wv, v, bv, MM, DD, DD, 0, 0, 0);

    // 2) Per-batch Gram matrix G[b] = q[b] * k[b]^T   (replaces the FFT)
    sgemm<true,false><<<dim3(LL/128, LL/128, BB), 256>>>(
        q, k, G, nullptr, LL, LL, DD,
        (size_t)LL*DD, (size_t)LL*DD, (size_t)LL*LL);

    // 3) mean_value[b,l] = (1/D) * sum_t G[b,t,(t-l) mod L]
    lag_partial<<<dim3(LL/256, 8, BB), 256>>>();
    lag_reduce<<<(BB*LL)/256, 256>>>();

    // 4) top-7 + softmax weights; batch-0 delays
    topk_softmax<<<BB, 256>>>();

    // 5) delay aggregation of v  (result reuses g_G)
    roll_combine<<<dim3(LL, BB), 256>>>();

    // 6) attn = roll_out @ Wo + bo  (into g_q)
    sgemm<false,false><<<dim3(DD/128, MM/128, 1), 256>>>(G, Wo, q, bo, MM, DD, DD, 0, 0, 0);

    // 7) x1 = LN(x + attn)  (into g_k)
    add_ln<<<MM, 256>>>(x, q, ln1g, ln1b, k);

    // 8) FFN: h = relu(x1 @ c1_w + c1_b)
    sgemm<false,true><<<dim3(FF/128, MM/128, 1), 256>>>(k, c1w, h, c1b, MM, FF, DD, 0, 0, 0);

    // 9) y = h @ c2_w + c2_b  (into g_v)
    sgemm<false,false><<<dim3(DD/128, MM/128, 1), 256>>>(h, c2w, v, c2b, MM, DD, FF, 0, 0, 0);

    // 10) out = LN(x1 + y)
    add_ln<<<MM, 256>>>(k, v, ln2g, ln2b, out);
}

// round 6
// speedup vs baseline: 2.3630x; 2.3630x over previous
#include <cuda_runtime.h>
#include <cuda_bf16.h>
#include <math.h>

#define BB 8
#define LL 2048
#define DD 1024
#define FF 4096
#define MM 16384
#define TOPK 7
#define LMASK 2047

typedef unsigned short u16;
typedef unsigned int   u32;

// ---------------- device scratch (row-major bf16 hi/lo) -------------------
__device__ u16 t_x_hi[(size_t)MM*DD],  t_x_lo[(size_t)MM*DD];
__device__ u16 t_q_hi[(size_t)MM*DD],  t_q_lo[(size_t)MM*DD];
__device__ u16 t_k_hi[(size_t)MM*DD],  t_k_lo[(size_t)MM*DD];
__device__ u16 t_r_hi[(size_t)MM*DD],  t_r_lo[(size_t)MM*DD];
__device__ u16 t_x1_hi[(size_t)MM*DD], t_x1_lo[(size_t)MM*DD];
__device__ u16 t_h_hi[(size_t)MM*FF],  t_h_lo[(size_t)MM*FF];
__device__ u16 t_wq_hi[DD*DD], t_wq_lo[DD*DD];
__device__ u16 t_wk_hi[DD*DD], t_wk_lo[DD*DD];
__device__ u16 t_wv_hi[DD*DD], t_wv_lo[DD*DD];
__device__ u16 t_wo_hi[DD*DD], t_wo_lo[DD*DD];
__device__ u16 t_c1_hi[(size_t)FF*DD], t_c1_lo[(size_t)FF*DD];
__device__ u16 t_c2_hi[(size_t)DD*FF], t_c2_lo[(size_t)DD*FF];

__device__ float g_v[(size_t)MM*DD];     // v; later reused for y
__device__ float g_G[(size_t)BB*LL*LL];  // Gram; later reused for attn
__device__ float g_x1[(size_t)MM*DD];
__device__ float g_part[BB*8*LL];
__device__ float g_mv[BB*LL];
__device__ float g_w[BB*8];
__device__ int   g_delay[8];

// ---------------- helpers --------------------------------------------------
__device__ __forceinline__ u32 smem_u32(const void* p) {
    u32 a;
    asm("{ .reg .u64 t; cvta.to.shared.u64 t, %1; cvt.u32.u64 %0, t; }"
        : "=r"(a) : "l"(p));
    return a;
}

__device__ __forceinline__ void split2(float v0, float v1, u32& h, u32& l) {
    __nv_bfloat16 h0 = __float2bfloat16(v0), h1 = __float2bfloat16(v1);
    __nv_bfloat16 l0 = __float2bfloat16(v0 - __bfloat162float(h0));
    __nv_bfloat16 l1 = __float2bfloat16(v1 - __bfloat162float(h1));
    h = (u32)__bfloat16_as_ushort(h0) | ((u32)__bfloat16_as_ushort(h1) << 16);
    l = (u32)__bfloat16_as_ushort(l0) | ((u32)__bfloat16_as_ushort(l1) << 16);
}

__device__ __forceinline__ void split_pack8(const float* v, uint4& hv, uint4& lv) {
    u32 h[4], l[4];
    #pragma unroll
    for (int p = 0; p < 4; p++) split2(v[2*p], v[2*p+1], h[p], l[p]);
    hv = make_uint4(h[0], h[1], h[2], h[3]);
    lv = make_uint4(l[0], l[1], l[2], l[3]);
}

#define CP16(sp, gp) \
    asm volatile("cp.async.cg.shared.global [%0], [%1], 16;" \
        :: "r"(smem_u32(sp)), "l"(gp))

#define MMA(c, a, b) \
    asm volatile("mma.sync.aligned.m16n8k16.row.col.f32.bf16.bf16.f32 " \
        "{%0,%1,%2,%3},{%4,%5,%6,%7},{%8,%9},{%0,%1,%2,%3};" \
        : "+f"((c)[0]), "+f"((c)[1]), "+f"((c)[2]), "+f"((c)[3]) \
        : "r"((a)[0]), "r"((a)[1]), "r"((a)[2]), "r"((a)[3]), \
          "r"((b)[0]), "r"((b)[1]))

// ---------------- GEMM: C[M,N] = A[M,K] @ B[N,K]^T (+bias, +relu) ---------
// A,B = bf16 hi/lo row-major. 3-term compensated product, fp32 accum.
// CTA 128x128, 8 warps x (64x32), K-chunk 32, 3-stage cp.async pipeline.
#define KC 32
#define PADH 40
#define TILEH (128*PADH)
#define STAGEH (4*TILEH)
#define GSMEM (3*STAGEH*2)

template<int OMODE>  // 0 = fp32 out, 1 = split out, 2 = split+relu out
__global__ __launch_bounds__(256) void gemm_mma(
    const u16* __restrict__ Ahi, const u16* __restrict__ Alo,
    const u16* __restrict__ Bhi, const u16* __restrict__ Blo,
    const float* __restrict__ bias, float* __restrict__ C,
    u16* __restrict__ Ohi, u16* __restrict__ Olo,
    int K, int ldc, int aRows, int bRows, size_t cBatch)
{
    extern __shared__ u16 sm[];
    const int tid = threadIdx.x;
    const int lane = tid & 31, warp = tid >> 5;
    const int wm = warp >> 2, wn = warp & 3;
    const int bx = blockIdx.x, by = blockIdx.y, bz = blockIdx.z;

    const u16* Ah = Ahi + (size_t)(bz * aRows + by * 128) * K;
    const u16* Al = Alo + (size_t)(bz * aRows + by * 128) * K;
    const u16* Bh = Bhi + (size_t)(bz * bRows + bx * 128) * K;
    const u16* Bl = Blo + (size_t)(bz * bRows + bx * 128) * K;

    const int nC = K >> 5;
    float acc[4][4][4];
    #pragma unroll
    for (int i = 0; i < 4; i++)
        #pragma unroll
        for (int j = 0; j < 4; j++)
            #pragma unroll
            for (int p = 0; p < 4; p++) acc[i][j][p] = 0.f;

    auto load_chunk = [&](int c, int s) {
        u16* st = sm + s * STAGEH;
        int k0 = c * KC;
        #pragma unroll
        for (int t = 0; t < 2; t++) {
            int widx = (t << 8) + tid;
            int row = widx >> 2, c16 = widx & 3;
            size_t go = (size_t)row * K + k0 + c16 * 8;
            int so = row * PADH + c16 * 8;
            CP16(st + so,             Ah + go);
            CP16(st + TILEH + so,     Al + go);
            CP16(st + 2 * TILEH + so, Bh + go);
            CP16(st + 3 * TILEH + so, Bl + go);
        }
        asm volatile("cp.async.commit_group;" ::: "memory");
    };

    load_chunk(0, 0);
    if (nC > 1) load_chunk(1, 1);

    for (int c = 0; c < nC; c++) {
        if (c == nC - 1) asm volatile("cp.async.wait_group 0;" ::: "memory");
        else             asm volatile("cp.async.wait_group 1;" ::: "memory");
        __syncthreads();
        if (c + 2 < nC) load_chunk(c + 2, (c + 2) % 3);

        u16* st = sm + (c % 3) * STAGEH;
        #pragma unroll
        for (int ks = 0; ks < 2; ks++) {
            int ko = ks * 16;
            u32 a_h[4][4], a_l[4][4], b_h[4][2], b_l[4][2];
            #pragma unroll
            for (int mi = 0; mi < 4; mi++) {
                int r = wm * 64 + mi * 16 + (lane & 15);
                int kk = ko + ((lane >> 4) << 3);
                u32 ad = smem_u32(st + r * PADH + kk);
                asm volatile("ldmatrix.sync.aligned.m8n8.x4.shared.b16 {%0,%1,%2,%3}, [%4];"
                    : "=r"(a_h[mi][0]), "=r"(a_h[mi][1]), "=r"(a_h[mi][2]), "=r"(a_h[mi][3])
                    : "r"(ad));
                u32 ad2 = smem_u32(st + TILEH + r * PADH + kk);
                asm volatile("ldmatrix.sync.aligned.m8n8.x4.shared.b16 {%0,%1,%2,%3}, [%4];"
                    : "=r"(a_l[mi][0]), "=r"(a_l[mi][1]), "=r"(a_l[mi][2]), "=r"(a_l[mi][3])
                    : "r"(ad2));
            }
            #pragma unroll
            for (int ni = 0; ni < 4; ni++) {
                int r = wn * 32 + ni * 8 + (lane & 7);
                int kk = ko + (((lane >> 3) & 1) << 3);
                u32 bd = smem_u32(st + 2 * TILEH + r * PADH + kk);
                asm volatile("ldmatrix.sync.aligned.m8n8.x2.shared.b16 {%0,%1}, [%2];"
                    : "=r"(b_h[ni][0]), "=r"(b_h[ni][1]) : "r"(bd));
                u32 bd2 = smem_u32(st + 3 * TILEH + r * PADH + kk);
                asm volatile("ldmatrix.sync.aligned.m8n8.x2.shared.b16 {%0,%1}, [%2];"
                    : "=r"(b_l[ni][0]), "=r"(b_l[ni][1]) : "r"(bd2));
            }
            #pragma unroll
            for (int mi = 0; mi < 4; mi++)
                #pragma unroll
                for (int ni = 0; ni < 4; ni++) {
                    MMA(acc[mi][ni], a_h[mi], b_h[ni]);
                    MMA(acc[mi][ni], a_h[mi], b_l[ni]);
                    MMA(acc[mi][ni], a_l[mi], b_h[ni]);
                }
        }
    }

    // epilogue
    const int r0 = by * 128 + wm * 64;
    const int c0b = bx * 128 + wn * 32;
    #pragma unroll
    for (int mi = 0; mi < 4; mi++) {
        #pragma unroll
        for (int ni = 0; ni < 4; ni++) {
            int rA = r0 + mi * 16 + (lane >> 2);
            int cc = c0b + ni * 8 + (lane & 3) * 2;
            float v0 = acc[mi][ni][0], v1 = acc[mi][ni][1];
            float v2 = acc[mi][ni][2], v3 = acc[mi][ni][3];
            if (bias) {
                float bb0 = __ldg(bias + cc), bb1 = __ldg(bias + cc + 1);
                v0 += bb0; v1 += bb1; v2 += bb0; v3 += bb1;
            }
            if (OMODE == 2) {
                v0 = fmaxf(v0, 0.f); v1 = fmaxf(v1, 0.f);
                v2 = fmaxf(v2, 0.f); v3 = fmaxf(v3, 0.f);
            }
            if (OMODE == 0) {
                float* Cz = C + bz * cBatch;
                *(float2*)(Cz + (size_t)rA * ldc + cc)       = make_float2(v0, v1);
                *(float2*)(Cz + (size_t)(rA + 8) * ldc + cc) = make_float2(v2, v3);
            } else {
                u32 h0, l0, h1, l1;
                split2(v0, v1, h0, l0);
                split2(v2, v3, h1, l1);
                *(u32*)(Ohi + (size_t)rA * ldc + cc)       = h0;
                *(u32*)(Olo + (size_t)rA * ldc + cc)       = l0;
                *(u32*)(Ohi + (size_t)(rA + 8) * ldc + cc) = h1;
                *(u32*)(Olo + (size_t)(rA + 8) * ldc + cc) = l1;
            }
        }
    }
}

// ---------------- splits ---------------------------------------------------
__global__ __launch_bounds__(256) void split_x(
    const float* __restrict__ s, u16* __restrict__ hi, u16* __restrict__ lo)
{
    size_t i = ((size_t)blockIdx.x * 256 + threadIdx.x) * 4;
    float4 v = *(const float4*)(s + i);
    u32 h0, l0, h1, l1;
    split2(v.x, v.y, h0, l0);
    split2(v.z, v.w, h1, l1);
    *(uint2*)(hi + i) = make_uint2(h0, h1);
    *(uint2*)(lo + i) = make_uint2(l0, l1);
}

// W[K,N] row-major -> out[N,K] hi/lo (transpose + split)
__global__ __launch_bounds__(256) void wsplit(
    const float* __restrict__ W, u16* __restrict__ hi, u16* __restrict__ lo,
    int K, int N)
{
    __shared__ float t[32][33];
    int n0 = blockIdx.x * 32, k0 = blockIdx.y * 32;
    int tx = threadIdx.x & 31, ty = threadIdx.x >> 5;
    #pragma unroll
    for (int j = 0; j < 32; j += 8)
        t[ty + j][tx] = W[(size_t)(k0 + ty + j) * N + n0 + tx];
    __syncthreads();
    #pragma unroll
    for (int j = 0; j < 32; j += 8) {
        float v = t[tx][ty + j];  // k = k0+tx, n = n0+ty+j
        __nv_bfloat16 h = __float2bfloat16(v);
        __nv_bfloat16 l = __float2bfloat16(v - __bfloat162float(h));
        size_t o = (size_t)(n0 + ty + j) * K + k0 + tx;
        hi[o] = __bfloat16_as_ushort(h);
        lo[o] = __bfloat16_as_ushort(l);
    }
}

// ---------------- lag / topk / roll / layernorm ---------------------------
__global__ void lag_partial()
{
    int b = blockIdx.z, tc = blockIdx.y;
    int l = blockIdx.x * 256 + threadIdx.x;
    const float* Gb = g_G + (size_t)b * LL * LL;
    int t0 = tc * 256;
    float s = 0.f;
    #pragma unroll 4
    for (int t = t0; t < t0 + 256; ++t)
        s += Gb[(size_t)t * LL + ((t - l) & LMASK)];
    g_part[(b * 8 + tc) * LL + l] = s;
}

__global__ void lag_reduce()
{
    int idx = blockIdx.x * 256 + threadIdx.x;
    int b = idx >> 11;
    float s = 0.f;
    #pragma unroll
    for (int tc = 0; tc < 8; tc++) s += g_part[(b * 8 + tc) * LL + (idx & LMASK)];
    g_mv[idx] = s * (1.f / (float)DD);
}

__global__ void topk_softmax()
{
    int b = blockIdx.x, tid = threadIdx.x;
    __shared__ float vals[LL];
    __shared__ float rv[256];
    __shared__ int   ri[256];
    __shared__ float topv[TOPK];
    __shared__ int   topi[TOPK];

    for (int i = tid; i < LL; i += 256) vals[i] = g_mv[b * LL + i];
    __syncthreads();
    for (int it = 0; it < TOPK; ++it) {
        float bv = -INFINITY; int bi = 0;
        for (int i = tid; i < LL; i += 256) {
            float v = vals[i];
            if (v > bv) { bv = v; bi = i; }
        }
        rv[tid] = bv; ri[tid] = bi;
        __syncthreads();
        for (int s = 128; s > 0; s >>= 1) {
            if (tid < s) {
                if (rv[tid+s] > rv[tid] ||
                    (rv[tid+s] == rv[tid] && ri[tid+s] < ri[tid])) {
                    rv[tid] = rv[tid+s]; ri[tid] = ri[tid+s];
                }
            }
            __syncthreads();
        }
        if (tid == 0) { topv[it] = rv[0]; topi[it] = ri[0]; vals[ri[0]] = -INFINITY; }
        __syncthreads();
    }
    if (tid == 0) {
        float mx = topv[0], e[TOPK], s = 0.f;
        #pragma unroll
        for (int i = 0; i < TOPK; i++) { e[i] = expf(topv[i] - mx); s += e[i]; }
        float inv = 1.f / s;
        #pragma unroll
        for (int i = 0; i < TOPK; i++) g_w[b * 8 + i] = e[i] * inv;
        if (b == 0)
            #pragma unroll
            for (int i = 0; i < TOPK; i++) g_delay[i] = topi[i];
    }
}

// rolled[b,l,:] = sum_i w[b,i]*v[b,(l+d_i)%L,:] -> split row-major
__global__ __launch_bounds__(128) void roll_combine()
{
    int l = blockIdx.x, b = blockIdx.y, tid = threadIdx.x;
    float w[TOPK]; int rows[TOPK];
    #pragma unroll
    for (int i = 0; i < TOPK; i++) {
        w[i] = g_w[b * 8 + i];
        rows[i] = (l + g_delay[i]) & LMASK;
    }
    int d0 = tid * 8;
    float acc[8] = {0,0,0,0,0,0,0,0};
    #pragma unroll
    for (int i = 0; i < TOPK; i++) {
        const float* vp = g_v + ((size_t)(b * LL + rows[i])) * DD + d0;
        float4 p0 = *(const float4*)vp, p1 = *(const float4*)(vp + 4);
        acc[0] = fmaf(w[i], p0.x, acc[0]); acc[1] = fmaf(w[i], p0.y, acc[1]);
        acc[2] = fmaf(w[i], p0.z, acc[2]); acc[3] = fmaf(w[i], p0.w, acc[3]);
        acc[4] = fmaf(w[i], p1.x, acc[4]); acc[5] = fmaf(w[i], p1.y, acc[5]);
        acc[6] = fmaf(w[i], p1.z, acc[6]); acc[7] = fmaf(w[i], p1.w, acc[7]);
    }
    size_t base = (size_t)(b * LL + l) * DD + d0;
    uint4 hv, lv; split_pack8(acc, hv, lv);
    *(uint4*)(t_r_hi + base) = hv;
    *(uint4*)(t_r_lo + base) = lv;
}

// out = LN(A + B); SPLIT also emits bf16 hi/lo row-major
template<int SPLIT>
__global__ __launch_bounds__(128) void add_ln(
    const float* __restrict__ A, const float* __restrict__ Bv,
    const float* __restrict__ g, const float* __restrict__ bt,
    float* __restrict__ out, u16* __restrict__ Ohi, u16* __restrict__ Olo)
{
    int row = blockIdx.x, tid = threadIdx.x;
    const float* pa = A  + (size_t)row * DD;
    const float* pb = Bv + (size_t)row * DD;
    __shared__ float red[128];
    int c0 = tid * 8;

    float v[8];
    float4 a0 = *(const float4*)(pa + c0), a1 = *(const float4*)(pa + c0 + 4);
    float4 b0 = *(const float4*)(pb + c0), b1 = *(const float4*)(pb + c0 + 4);
    v[0]=a0.x+b0.x; v[1]=a0.y+b0.y; v[2]=a0.z+b0.z; v[3]=a0.w+b0.w;
    v[4]=a1.x+b1.x; v[5]=a1.y+b1.y; v[6]=a1.z+b1.z; v[7]=a1.w+b1.w;
    float s = 0.f;
    #pragma unroll
    for (int j = 0; j < 8; j++) s += v[j];
    red[tid] = s; __syncthreads();
    for (int st = 64; st > 0; st >>= 1) {
        if (tid < st) red[tid] += red[tid + st];
        __syncthreads();
    }
    float mean = red[0] * (1.f / (float)DD);
    __syncthreads();
    float vs = 0.f;
    #pragma unroll
    for (int j = 0; j < 8; j++) { float d = v[j] - mean; vs += d * d; }
    red[tid] = vs; __syncthreads();
    for (int st = 64; st > 0; st >>= 1) {
        if (tid < st) red[tid] += red[tid + st];
        __syncthreads();
    }
    float rstd = rsqrtf(red[0] * (1.f / (float)DD) + 1e-6f);

    float o[8];
    #pragma unroll
    for (int j = 0; j < 8; j++)
        o[j] = (v[j] - mean) * rstd * g[c0 + j] + bt[c0 + j];
    float* po = out + (size_t)row * DD;
    *(float4*)(po + c0)     = make_float4(o[0], o[1], o[2], o[3]);
    *(float4*)(po + c0 + 4) = make_float4(o[4], o[5], o[6], o[7]);

    if (SPLIT) {
        size_t base = (size_t)row * DD + c0;
        uint4 hv, lv; split_pack8(o, hv, lv);
        *(uint4*)(Ohi + base) = hv;
        *(uint4*)(Olo + base) = lv;
    }
}

// -------------------------------------------------------------------------
#define SYM(p, s) cudaGetSymbolAddress((void**)&p, s)

extern "C" void kernel_launch(void* const* d_in, const int* in_sizes, int n_in,
                              void* d_out, int out_size)
{
    const float* x    = (const float*)d_in[0];
    const float* Wq   = (const float*)d_in[1];
    const float* bq   = (const float*)d_in[2];
    const float* Wk   = (const float*)d_in[3];
    const float* bk   = (const float*)d_in[4];
    const float* Wv   = (const float*)d_in[5];
    const float* bv   = (const float*)d_in[6];
    const float* Wo   = (const float*)d_in[7];
    const float* bo   = (const float*)d_in[8];
    const float* ln1g = (const float*)d_in[9];
    const float* ln1b = (const float*)d_in[10];
    const float* c1w  = (const float*)d_in[11];
    const float* c1b  = (const float*)d_in[12];
    const float* c2w  = (const float*)d_in[13];
    const float* c2b  = (const float*)d_in[14];
    const float* ln2g = (const float*)d_in[15];
    const float* ln2b = (const float*)d_in[16];
    float* out = (float*)d_out;

    cudaFuncSetAttribute(gemm_mma<0>, cudaFuncAttributeMaxDynamicSharedMemorySize, GSMEM);
    cudaFuncSetAttribute(gemm_mma<1>, cudaFuncAttributeMaxDynamicSharedMemorySize, GSMEM);
    cudaFuncSetAttribute(gemm_mma<2>, cudaFuncAttributeMaxDynamicSharedMemorySize, GSMEM);

    u16 *xh,*xl,*qh,*ql,*kh,*kl,*rh,*rl,*x1h,*x1l,*hh,*hl;
    u16 *wqh,*wql,*wkh,*wkl,*wvh,*wvl,*woh,*wol,*c1h,*c1l,*c2h,*c2l;
    float *v, *G, *x1;
    SYM(xh, t_x_hi);   SYM(xl, t_x_lo);
    SYM(qh, t_q_hi);   SYM(ql, t_q_lo);
    SYM(kh, t_k_hi);   SYM(kl, t_k_lo);
    SYM(rh, t_r_hi);   SYM(rl, t_r_lo);
    SYM(x1h, t_x1_hi); SYM(x1l, t_x1_lo);
    SYM(hh, t_h_hi);   SYM(hl, t_h_lo);
    SYM(wqh, t_wq_hi); SYM(wql, t_wq_lo);
    SYM(wkh, t_wk_hi); SYM(wkl, t_wk_lo);
    SYM(wvh, t_wv_hi); SYM(wvl, t_wv_lo);
    SYM(woh, t_wo_hi); SYM(wol, t_wo_lo);
    SYM(c1h, t_c1_hi); SYM(c1l, t_c1_lo);
    SYM(c2h, t_c2_hi); SYM(c2l, t_c2_lo);
    SYM(v, g_v); SYM(G, g_G); SYM(x1, g_x1);

    // split x; transpose+split weights
    split_x<<<(MM*DD)/1024, 256>>>(x, xh, xl);
    wsplit<<<dim3(DD/32, DD/32), 256>>>(Wq, wqh, wql, DD, DD);
    wsplit<<<dim3(DD/32, DD/32), 256>>>(Wk, wkh, wkl, DD, DD);
    wsplit<<<dim3(DD/32, DD/32), 256>>>(Wv, wvh, wvl, DD, DD);
    wsplit<<<dim3(DD/32, DD/32), 256>>>(Wo, woh, wol, DD, DD);
    wsplit<<<dim3(FF/32, DD/32), 256>>>(c1w, c1h, c1l, DD, FF);
    wsplit<<<dim3(DD/32, FF/32), 256>>>(c2w, c2h, c2l, FF, DD);

    // QKV
    gemm_mma<1><<<dim3(8,128,1), 256, GSMEM>>>(xh, xl, wqh, wql, bq,
        nullptr, qh, ql, DD, DD, 0, 0, 0);
    gemm_mma<1><<<dim3(8,128,1), 256, GSMEM>>>(xh, xl, wkh, wkl, bk,
        nullptr, kh, kl, DD, DD, 0, 0, 0);
    gemm_mma<0><<<dim3(8,128,1), 256, GSMEM>>>(xh, xl, wvh, wvl, bv,
        v, nullptr, nullptr, DD, DD, 0, 0, 0);

    // Gram G[b] = q[b] @ k[b]^T
    gemm_mma<0><<<dim3(16,16,8), 256, GSMEM>>>(qh, ql, kh, kl, nullptr,
        G, nullptr, nullptr, DD, LL, LL, LL, (size_t)LL*LL);

    lag_partial<<<dim3(LL/256, 8, BB), 256>>>();
    lag_reduce<<<(BB*LL)/256, 256>>>();
    topk_softmax<<<BB, 256>>>();
    roll_combine<<<dim3(LL, BB), 128>>>();

    // attn = rolled @ Wo + bo  (fp32 into G, reused)
    gemm_mma<0><<<dim3(8,128,1), 256, GSMEM>>>(rh, rl, woh, wol, bo,
        G, nullptr, nullptr, DD, DD, 0, 0, 0);

    // x1 = LN(x + attn) (+ split)
    add_ln<1><<<MM, 128>>>(x, G, ln1g, ln1b, x1, x1h, x1l);

    // h = relu(x1 @ c1 + b)
    gemm_mma<2><<<dim3(32,128,1), 256, GSMEM>>>(x1h, x1l, c1h, c1l, c1b,
        nullptr, hh, hl, DD, FF, 0, 0, 0);

    // y = h @ c2 + b  (fp32 into v, reused)
    gemm_mma<0><<<dim3(8,128,1), 256, GSMEM>>>(hh, hl, c2h, c2l, c2b,
        v, nullptr, nullptr, FF, DD, 0, 0, 0);

    // out = LN(x1 + y)
    add_ln<0><<<MM, 128>>>(x1, v, ln2g, ln2b, out, nullptr, nullptr);
}

// round 8
// speedup vs baseline: 2.5864x; 1.0946x over previous
#include <cuda_runtime.h>
#include <cuda_bf16.h>
#include <math.h>

#define BB 8
#define LL 2048
#define DD 1024
#define FF 4096
#define MM 16384
#define TOPK 7
#define LMASK 2047

typedef unsigned short u16;
typedef unsigned int   u32;

// ---------------- device scratch (row-major bf16 hi/lo) -------------------
__device__ u16 t_x_hi[(size_t)MM*DD],  t_x_lo[(size_t)MM*DD];
__device__ u16 t_q_hi[(size_t)MM*DD],  t_q_lo[(size_t)MM*DD];
__device__ u16 t_k_hi[(size_t)MM*DD],  t_k_lo[(size_t)MM*DD];
__device__ u16 t_r_hi[(size_t)MM*DD],  t_r_lo[(size_t)MM*DD];
__device__ u16 t_x1_hi[(size_t)MM*DD], t_x1_lo[(size_t)MM*DD];
__device__ u16 t_h_hi[(size_t)MM*FF],  t_h_lo[(size_t)MM*FF];
__device__ u16 t_wq_hi[DD*DD], t_wq_lo[DD*DD];
__device__ u16 t_wk_hi[DD*DD], t_wk_lo[DD*DD];
__device__ u16 t_wv_hi[DD*DD], t_wv_lo[DD*DD];
__device__ u16 t_wo_hi[DD*DD], t_wo_lo[DD*DD];
__device__ u16 t_c1_hi[(size_t)FF*DD], t_c1_lo[(size_t)FF*DD];
__device__ u16 t_c2_hi[(size_t)DD*FF], t_c2_lo[(size_t)DD*FF];

__device__ float g_v[(size_t)MM*DD];     // v; later reused for y
__device__ float g_G[(size_t)BB*LL*LL];  // Gram; later reused for attn
__device__ float g_x1[(size_t)MM*DD];
__device__ float g_part[BB*8*LL];
__device__ float g_mv[BB*LL];
__device__ float g_w[BB*8];
__device__ int   g_delay[8];

// ---------------- helpers --------------------------------------------------
__device__ __forceinline__ u32 smem_u32(const void* p) {
    u32 a;
    asm("{ .reg .u64 t; cvta.to.shared.u64 t, %1; cvt.u32.u64 %0, t; }"
        : "=r"(a) : "l"(p));
    return a;
}

__device__ __forceinline__ void split2(float v0, float v1, u32& h, u32& l) {
    __nv_bfloat16 h0 = __float2bfloat16(v0), h1 = __float2bfloat16(v1);
    __nv_bfloat16 l0 = __float2bfloat16(v0 - __bfloat162float(h0));
    __nv_bfloat16 l1 = __float2bfloat16(v1 - __bfloat162float(h1));
    h = (u32)__bfloat16_as_ushort(h0) | ((u32)__bfloat16_as_ushort(h1) << 16);
    l = (u32)__bfloat16_as_ushort(l0) | ((u32)__bfloat16_as_ushort(l1) << 16);
}

__device__ __forceinline__ void split_pack8(const float* v, uint4& hv, uint4& lv) {
    u32 h[4], l[4];
    #pragma unroll
    for (int p = 0; p < 4; p++) split2(v[2*p], v[2*p+1], h[p], l[p]);
    hv = make_uint4(h[0], h[1], h[2], h[3]);
    lv = make_uint4(l[0], l[1], l[2], l[3]);
}

#define CPA(sa, gp) \
    asm volatile("cp.async.cg.shared.global [%0], [%1], 16;" \
        :: "r"(sa), "l"(gp))

#define MMA(c, a, b) \
    asm volatile("mma.sync.aligned.m16n8k16.row.col.f32.bf16.bf16.f32 " \
        "{%0,%1,%2,%3},{%4,%5,%6,%7},{%8,%9},{%0,%1,%2,%3};" \
        : "+f"((c)[0]), "+f"((c)[1]), "+f"((c)[2]), "+f"((c)[3]) \
        : "r"((a)[0]), "r"((a)[1]), "r"((a)[2]), "r"((a)[3]), \
          "r"((b)[0]), "r"((b)[1]))

#define LDSM4(r, a) \
    asm volatile("ldmatrix.sync.aligned.m8n8.x4.shared.b16 {%0,%1,%2,%3}, [%4];" \
        : "=r"((r)[0]), "=r"((r)[1]), "=r"((r)[2]), "=r"((r)[3]) : "r"(a))
#define LDSM2(r, a) \
    asm volatile("ldmatrix.sync.aligned.m8n8.x2.shared.b16 {%0,%1}, [%2];" \
        : "=r"((r)[0]), "=r"((r)[1]) : "r"(a))

// ---------------- GEMM: C[M,N] = A[M,K] @ B[N,K]^T (+bias, +relu) ---------
// A,B = bf16 hi/lo row-major. 3-term compensated product, fp32 accum.
// CTA 256x128, 16 warps x (64x32), K-chunk 32, 3-stage cp.async pipeline.
#define KC 32
#define PADH 40
// byte offsets within one stage
#define OFF_AL 20480u   // 256*40*2
#define OFF_BH 40960u
#define OFF_BL 51200u   // + 128*40*2
#define STAGE_B 61440u
#define GSMEM (3*61440)

template<int OMODE>  // 0 = fp32 out, 1 = split out, 2 = split+relu out
__global__ __launch_bounds__(512) void gemm_mma(
    const u16* __restrict__ Ahi, const u16* __restrict__ Alo,
    const u16* __restrict__ Bhi, const u16* __restrict__ Blo,
    const float* __restrict__ bias, float* __restrict__ C,
    u16* __restrict__ Ohi, u16* __restrict__ Olo,
    int K, int ldc, int aRows, int bRows, size_t cBatch)
{
    extern __shared__ u16 sm[];
    const int tid = threadIdx.x;
    const int lane = tid & 31, warp = tid >> 5;   // warp 0..15
    const int wm = warp >> 2, wn = warp & 3;
    const int bx = blockIdx.x, by = blockIdx.y, bz = blockIdx.z;

    const u16* Ah = Ahi + (size_t)(bz * aRows + by * 256) * K;
    const u16* Al = Alo + (size_t)(bz * aRows + by * 256) * K;
    const u16* Bh = Bhi + (size_t)(bz * bRows + bx * 128) * K;
    const u16* Bl = Blo + (size_t)(bz * bRows + bx * 128) * K;

    const u32 smBase = smem_u32(sm);
    const int nC = K >> 5;

    float acc[4][4][4];
    #pragma unroll
    for (int i = 0; i < 4; i++)
        #pragma unroll
        for (int j = 0; j < 4; j++)
            #pragma unroll
            for (int p = 0; p < 4; p++) acc[i][j][p] = 0.f;

    auto load_chunk = [&](int c, int s) {
        u32 st = smBase + s * STAGE_B;
        int k0 = c * KC;
        // A: 256 rows x 4 x 16B per tile -> 1024 ops, 2 iters of 512 thr
        #pragma unroll
        for (int t = 0; t < 2; t++) {
            int idx = (t << 9) + tid;
            int row = idx >> 2, c16 = idx & 3;
            size_t go = (size_t)row * K + k0 + c16 * 8;
            u32 so = st + (u32)(row * PADH + c16 * 8) * 2;
            CPA(so, Ah + go);
            CPA(so + OFF_AL, Al + go);
        }
        // B: 128 rows x 4 -> 512 ops, 1 iter
        {
            int row = tid >> 2, c16 = tid & 3;
            size_t go = (size_t)row * K + k0 + c16 * 8;
            u32 so = st + OFF_BH + (u32)(row * PADH + c16 * 8) * 2;
            CPA(so, Bh + go);
            CPA(so + (OFF_BL - OFF_BH), Bl + go);
        }
        asm volatile("cp.async.commit_group;" ::: "memory");
    };

    load_chunk(0, 0);
    if (nC > 1) load_chunk(1, 1);

    for (int c = 0; c < nC; c++) {
        if (c == nC - 1) asm volatile("cp.async.wait_group 0;" ::: "memory");
        else             asm volatile("cp.async.wait_group 1;" ::: "memory");
        __syncthreads();
        if (c + 2 < nC) load_chunk(c + 2, (c + 2) % 3);

        u32 st = smBase + (u32)(c % 3) * STAGE_B;
        #pragma unroll
        for (int ks = 0; ks < 2; ks++) {
            int ko = ks * 16;
            // B fragments for this ks (16 regs)
            u32 b_h[4][2], b_l[4][2];
            #pragma unroll
            for (int ni = 0; ni < 4; ni++) {
                int r = wn * 32 + ni * 8 + (lane & 7);
                int kk = ko + (((lane >> 3) & 1) << 3);
                u32 ba = st + OFF_BH + (u32)(r * PADH + kk) * 2;
                LDSM2(b_h[ni], ba);
                LDSM2(b_l[ni], ba + (OFF_BL - OFF_BH));
            }
            // A fragments per mi (8 regs live at a time)
            #pragma unroll
            for (int mi = 0; mi < 4; mi++) {
                int r = wm * 64 + mi * 16 + (lane & 15);
                int kk = ko + ((lane >> 4) << 3);
                u32 aa = st + (u32)(r * PADH + kk) * 2;
                u32 a_h[4], a_l[4];
                LDSM4(a_h, aa);
                LDSM4(a_l, aa + OFF_AL);
                #pragma unroll
                for (int ni = 0; ni < 4; ni++) {
                    MMA(acc[mi][ni], a_h, b_h[ni]);
                    MMA(acc[mi][ni], a_h, b_l[ni]);
                    MMA(acc[mi][ni], a_l, b_h[ni]);
                }
            }
        }
    }

    // epilogue
    const int r0 = by * 256 + wm * 64;
    const int c0b = bx * 128 + wn * 32;
    #pragma unroll
    for (int mi = 0; mi < 4; mi++) {
        #pragma unroll
        for (int ni = 0; ni < 4; ni++) {
            int rA = r0 + mi * 16 + (lane >> 2);
            int cc = c0b + ni * 8 + (lane & 3) * 2;
            float v0 = acc[mi][ni][0], v1 = acc[mi][ni][1];
            float v2 = acc[mi][ni][2], v3 = acc[mi][ni][3];
            if (bias) {
                float bb0 = __ldg(bias + cc), bb1 = __ldg(bias + cc + 1);
                v0 += bb0; v1 += bb1; v2 += bb0; v3 += bb1;
            }
            if (OMODE == 2) {
                v0 = fmaxf(v0, 0.f); v1 = fmaxf(v1, 0.f);
                v2 = fmaxf(v2, 0.f); v3 = fmaxf(v3, 0.f);
            }
            if (OMODE == 0) {
                float* Cz = C + bz * cBatch;
                *(float2*)(Cz + (size_t)rA * ldc + cc)       = make_float2(v0, v1);
                *(float2*)(Cz + (size_t)(rA + 8) * ldc + cc) = make_float2(v2, v3);
            } else {
                u32 h0, l0, h1, l1;
                split2(v0, v1, h0, l0);
                split2(v2, v3, h1, l1);
                *(u32*)(Ohi + (size_t)rA * ldc + cc)       = h0;
                *(u32*)(Olo + (size_t)rA * ldc + cc)       = l0;
                *(u32*)(Ohi + (size_t)(rA + 8) * ldc + cc) = h1;
                *(u32*)(Olo + (size_t)(rA + 8) * ldc + cc) = l1;
            }
        }
    }
}

// ---------------- splits ---------------------------------------------------
__global__ __launch_bounds__(256) void split_x(
    const float* __restrict__ s, u16* __restrict__ hi, u16* __restrict__ lo)
{
    size_t i = ((size_t)blockIdx.x * 256 + threadIdx.x) * 4;
    float4 v = *(const float4*)(s + i);
    u32 h0, l0, h1, l1;
    split2(v.x, v.y, h0, l0);
    split2(v.z, v.w, h1, l1);
    *(uint2*)(hi + i) = make_uint2(h0, h1);
    *(uint2*)(lo + i) = make_uint2(l0, l1);
}

// W[K,N] row-major -> out[N,K] hi/lo (transpose + split)
__global__ __launch_bounds__(256) void wsplit(
    const float* __restrict__ W, u16* __restrict__ hi, u16* __restrict__ lo,
    int K, int N)
{
    __shared__ float t[32][33];
    int n0 = blockIdx.x * 32, k0 = blockIdx.y * 32;
    int tx = threadIdx.x & 31, ty = threadIdx.x >> 5;
    #pragma unroll
    for (int j = 0; j < 32; j += 8)
        t[ty + j][tx] = W[(size_t)(k0 + ty + j) * N + n0 + tx];
    __syncthreads();
    #pragma unroll
    for (int j = 0; j < 32; j += 8) {
        float v = t[tx][ty + j];
        __nv_bfloat16 h = __float2bfloat16(v);
        __nv_bfloat16 l = __float2bfloat16(v - __bfloat162float(h));
        size_t o = (size_t)(n0 + ty + j) * K + k0 + tx;
        hi[o] = __bfloat16_as_ushort(h);
        lo[o] = __bfloat16_as_ushort(l);
    }
}

// ---------------- lag / topk / roll / layernorm ---------------------------
__global__ void lag_partial()
{
    int b = blockIdx.z, tc = blockIdx.y;
    int l = blockIdx.x * 256 + threadIdx.x;
    const float* Gb = g_G + (size_t)b * LL * LL;
    int t0 = tc * 256;
    float s = 0.f;
    #pragma unroll 4
    for (int t = t0; t < t0 + 256; ++t)
        s += Gb[(size_t)t * LL + ((t - l) & LMASK)];
    g_part[(b * 8 + tc) * LL + l] = s;
}

__global__ void lag_reduce()
{
    int idx = blockIdx.x * 256 + threadIdx.x;
    int b = idx >> 11;
    float s = 0.f;
    #pragma unroll
    for (int tc = 0; tc < 8; tc++) s += g_part[(b * 8 + tc) * LL + (idx & LMASK)];
    g_mv[idx] = s * (1.f / (float)DD);
}

__global__ void topk_softmax()
{
    int b = blockIdx.x, tid = threadIdx.x;
    __shared__ float vals[LL];
    __shared__ float rv[256];
    __shared__ int   ri[256];
    __shared__ float topv[TOPK];
    __shared__ int   topi[TOPK];

    for (int i = tid; i < LL; i += 256) vals[i] = g_mv[b * LL + i];
    __syncthreads();
    for (int it = 0; it < TOPK; ++it) {
        float bv = -INFINITY; int bi = 0;
        for (int i = tid; i < LL; i += 256) {
            float v = vals[i];
            if (v > bv) { bv = v; bi = i; }
        }
        rv[tid] = bv; ri[tid] = bi;
        __syncthreads();
        for (int s = 128; s > 0; s >>= 1) {
            if (tid < s) {
                if (rv[tid+s] > rv[tid] ||
                    (rv[tid+s] == rv[tid] && ri[tid+s] < ri[tid])) {
                    rv[tid] = rv[tid+s]; ri[tid] = ri[tid+s];
                }
            }
            __syncthreads();
        }
        if (tid == 0) { topv[it] = rv[0]; topi[it] = ri[0]; vals[ri[0]] = -INFINITY; }
        __syncthreads();
    }
    if (tid == 0) {
        float mx = topv[0], e[TOPK], s = 0.f;
        #pragma unroll
        for (int i = 0; i < TOPK; i++) { e[i] = expf(topv[i] - mx); s += e[i]; }
        float inv = 1.f / s;
        #pragma unroll
        for (int i = 0; i < TOPK; i++) g_w[b * 8 + i] = e[i] * inv;
        if (b == 0)
            #pragma unroll
            for (int i = 0; i < TOPK; i++) g_delay[i] = topi[i];
    }
}

// rolled[b,l,:] = sum_i w[b,i]*v[b,(l+d_i)%L,:] -> split row-major
__global__ __launch_bounds__(128) void roll_combine()
{
    int l = blockIdx.x, b = blockIdx.y, tid = threadIdx.x;
    float w[TOPK]; int rows[TOPK];
    #pragma unroll
    for (int i = 0; i < TOPK; i++) {
        w[i] = g_w[b * 8 + i];
        rows[i] = (l + g_delay[i]) & LMASK;
    }
    int d0 = tid * 8;
    float acc[8] = {0,0,0,0,0,0,0,0};
    #pragma unroll
    for (int i = 0; i < TOPK; i++) {
        const float* vp = g_v + ((size_t)(b * LL + rows[i])) * DD + d0;
        float4 p0 = *(const float4*)vp, p1 = *(const float4*)(vp + 4);
        acc[0] = fmaf(w[i], p0.x, acc[0]); acc[1] = fmaf(w[i], p0.y, acc[1]);
        acc[2] = fmaf(w[i], p0.z, acc[2]); acc[3] = fmaf(w[i], p0.w, acc[3]);
        acc[4] = fmaf(w[i], p1.x, acc[4]); acc[5] = fmaf(w[i], p1.y, acc[5]);
        acc[6] = fmaf(w[i], p1.z, acc[6]); acc[7] = fmaf(w[i], p1.w, acc[7]);
    }
    size_t base = (size_t)(b * LL + l) * DD + d0;
    uint4 hv, lv; split_pack8(acc, hv, lv);
    *(uint4*)(t_r_hi + base) = hv;
    *(uint4*)(t_r_lo + base) = lv;
}

// out = LN(A + B); SPLIT also emits bf16 hi/lo row-major
template<int SPLIT>
__global__ __launch_bounds__(128) void add_ln(
    const float* __restrict__ A, const float* __restrict__ Bv,
    const float* __restrict__ g, const float* __restrict__ bt,
    float* __restrict__ out, u16* __restrict__ Ohi, u16* __restrict__ Olo)
{
    int row = blockIdx.x, tid = threadIdx.x;
    const float* pa = A  + (size_t)row * DD;
    const float* pb = Bv + (size_t)row * DD;
    __shared__ float red[128];
    int c0 = tid * 8;

    float v[8];
    float4 a0 = *(const float4*)(pa + c0), a1 = *(const float4*)(pa + c0 + 4);
    float4 b0 = *(const float4*)(pb + c0), b1 = *(const float4*)(pb + c0 + 4);
    v[0]=a0.x+b0.x; v[1]=a0.y+b0.y; v[2]=a0.z+b0.z; v[3]=a0.w+b0.w;
    v[4]=a1.x+b1.x; v[5]=a1.y+b1.y; v[6]=a1.z+b1.z; v[7]=a1.w+b1.w;
    float s = 0.f;
    #pragma unroll
    for (int j = 0; j < 8; j++) s += v[j];
    red[tid] = s; __syncthreads();
    for (int st = 64; st > 0; st >>= 1) {
        if (tid < st) red[tid] += red[tid + st];
        __syncthreads();
    }
    float mean = red[0] * (1.f / (float)DD);
    __syncthreads();
    float vs = 0.f;
    #pragma unroll
    for (int j = 0; j < 8; j++) { float d = v[j] - mean; vs += d * d; }
    red[tid] = vs; __syncthreads();
    for (int st = 64; st > 0; st >>= 1) {
        if (tid < st) red[tid] += red[tid + st];
        __syncthreads();
    }
    float rstd = rsqrtf(red[0] * (1.f / (float)DD) + 1e-6f);

    float o[8];
    #pragma unroll
    for (int j = 0; j < 8; j++)
        o[j] = (v[j] - mean) * rstd * g[c0 + j] + bt[c0 + j];
    float* po = out + (size_t)row * DD;
    *(float4*)(po + c0)     = make_float4(o[0], o[1], o[2], o[3]);
    *(float4*)(po + c0 + 4) = make_float4(o[4], o[5], o[6], o[7]);

    if (SPLIT) {
        size_t base = (size_t)row * DD + c0;
        uint4 hv, lv; split_pack8(o, hv, lv);
        *(uint4*)(Ohi + base) = hv;
        *(uint4*)(Olo + base) = lv;
    }
}

// -------------------------------------------------------------------------
#define SYM(p, s) cudaGetSymbolAddress((void**)&p, s)

extern "C" void kernel_launch(void* const* d_in, const int* in_sizes, int n_in,
                              void* d_out, int out_size)
{
    const float* x    = (const float*)d_in[0];
    const float* Wq   = (const float*)d_in[1];
    const float* bq   = (const float*)d_in[2];
    const float* Wk   = (const float*)d_in[3];
    const float* bk   = (const float*)d_in[4];
    const float* Wv   = (const float*)d_in[5];
    const float* bv   = (const float*)d_in[6];
    const float* Wo   = (const float*)d_in[7];
    const float* bo   = (const float*)d_in[8];
    const float* ln1g = (const float*)d_in[9];
    const float* ln1b = (const float*)d_in[10];
    const float* c1w  = (const float*)d_in[11];
    const float* c1b  = (const float*)d_in[12];
    const float* c2w  = (const float*)d_in[13];
    const float* c2b  = (const float*)d_in[14];
    const float* ln2g = (const float*)d_in[15];
    const float* ln2b = (const float*)d_in[16];
    float* out = (float*)d_out;

    cudaFuncSetAttribute(gemm_mma<0>, cudaFuncAttributeMaxDynamicSharedMemorySize, GSMEM);
    cudaFuncSetAttribute(gemm_mma<1>, cudaFuncAttributeMaxDynamicSharedMemorySize, GSMEM);
    cudaFuncSetAttribute(gemm_mma<2>, cudaFuncAttributeMaxDynamicSharedMemorySize, GSMEM);

    u16 *xh,*xl,*qh,*ql,*kh,*kl,*rh,*rl,*x1h,*x1l,*hh,*hl;
    u16 *wqh,*wql,*wkh,*wkl,*wvh,*wvl,*woh,*wol,*c1h,*c1l,*c2h,*c2l;
    float *v, *G, *x1;
    SYM(xh, t_x_hi);   SYM(xl, t_x_lo);
    SYM(qh, t_q_hi);   SYM(ql, t_q_lo);
    SYM(kh, t_k_hi);   SYM(kl, t_k_lo);
    SYM(rh, t_r_hi);   SYM(rl, t_r_lo);
    SYM(x1h, t_x1_hi); SYM(x1l, t_x1_lo);
    SYM(hh, t_h_hi);   SYM(hl, t_h_lo);
    SYM(wqh, t_wq_hi); SYM(wql, t_wq_lo);
    SYM(wkh, t_wk_hi); SYM(wkl, t_wk_lo);
    SYM(wvh, t_wv_hi); SYM(wvl, t_wv_lo);
    SYM(woh, t_wo_hi); SYM(wol, t_wo_lo);
    SYM(c1h, t_c1_hi); SYM(c1l, t_c1_lo);
    SYM(c2h, t_c2_hi); SYM(c2l, t_c2_lo);
    SYM(v, g_v); SYM(G, g_G); SYM(x1, g_x1);

    // split x; transpose+split weights
    split_x<<<(MM*DD)/1024, 256>>>(x, xh, xl);
    wsplit<<<dim3(DD/32, DD/32), 256>>>(Wq, wqh, wql, DD, DD);
    wsplit<<<dim3(DD/32, DD/32), 256>>>(Wk, wkh, wkl, DD, DD);
    wsplit<<<dim3(DD/32, DD/32), 256>>>(Wv, wvh, wvl, DD, DD);
    wsplit<<<dim3(DD/32, DD/32), 256>>>(Wo, woh, wol, DD, DD);
    wsplit<<<dim3(FF/32, DD/32), 256>>>(c1w, c1h, c1l, DD, FF);
    wsplit<<<dim3(DD/32, FF/32), 256>>>(c2w, c2h, c2l, FF, DD);

    // QKV  (M=16384 -> 64 row blocks of 256)
    gemm_mma<1><<<dim3(8,64,1), 512, GSMEM>>>(xh, xl, wqh, wql, bq,
        nullptr, qh, ql, DD, DD, 0, 0, 0);
    gemm_mma<1><<<dim3(8,64,1), 512, GSMEM>>>(xh, xl, wkh, wkl, bk,
        nullptr, kh, kl, DD, DD, 0, 0, 0);
    gemm_mma<0><<<dim3(8,64,1), 512, GSMEM>>>(xh, xl, wvh, wvl, bv,
        v, nullptr, nullptr, DD, DD, 0, 0, 0);

    // Gram G[b] = q[b] @ k[b]^T  (M=N=2048 per batch)
    gemm_mma<0><<<dim3(16,8,8), 512, GSMEM>>>(qh, ql, kh, kl, nullptr,
        G, nullptr, nullptr, DD, LL, LL, LL, (size_t)LL*LL);

    lag_partial<<<dim3(LL/256, 8, BB), 256>>>();
    lag_reduce<<<(BB*LL)/256, 256>>>();
    topk_softmax<<<BB, 256>>>();
    roll_combine<<<dim3(LL, BB), 128>>>();

    // attn = rolled @ Wo + bo  (fp32 into G, reused)
    gemm_mma<0><<<dim3(8,64,1), 512, GSMEM>>>(rh, rl, woh, wol, bo,
        G, nullptr, nullptr, DD, DD, 0, 0, 0);

    // x1 = LN(x + attn) (+ split)
    add_ln<1><<<MM, 128>>>(x, G, ln1g, ln1b, x1, x1h, x1l);

    // h = relu(x1 @ c1 + b)
    gemm_mma<2><<<dim3(32,64,1), 512, GSMEM>>>(x1h, x1l, c1h, c1l, c1b,
        nullptr, hh, hl, DD, FF, 0, 0, 0);

    // y = h @ c2 + b  (fp32 into v, reused)
    gemm_mma<0><<<dim3(8,64,1), 512, GSMEM>>>(hh, hl, c2h, c2l, c2b,
        v, nullptr, nullptr, FF, DD, 0, 0, 0);

    // out = LN(x1 + y)
    add_ln<0><<<MM, 128>>>(x1, v, ln2g, ln2b, out, nullptr, nullptr);
}